// round 15
// baseline (speedup 1.0000x reference)
#include <cuda_runtime.h>
#include <cuda_fp16.h>

// GatheringLoss — R15: maximize per-warp MMA chain ILP. BM=128, 256thr/8 warps,
// warp = 16 rows x FULL 128-key chunk -> acc[16][4] = 16 independent HMMA
// chains (R4 evidence: 16 chains -> 6.8 cyc/MMA vs 10.2 at 8 chains).
// Single barrier per chunk, guarded top-2, exact fp32 rescore epilogue.
// out = [kg (65536) | vg (65536)]

#define T_TOTAL 65536
#define M_KEYS  1024
#define C_DIM   128
#define BM      128
#define THREADS 256
#define SAB     272                 // smem row stride (bytes)

#define OFF_A     0                 // 128 rows * 272B = 34816
#define OFF_B(buf) (34816 + (buf) * 34816)   // 128 keys * 272B per buffer
#define SM_TOTAL  104448            // 102 KB -> 2 CTAs/SM

__device__ __half g_keys_h[M_KEYS * C_DIM];

__device__ __forceinline__ unsigned smem_u32(const void* p) {
    unsigned a;
    asm("{ .reg .u64 t; cvta.to.shared.u64 t, %1; cvt.u32.u64 %0, t; }" : "=r"(a) : "l"(p));
    return a;
}

#define LDSM_X4(r0, r1, r2, r3, a)                                             \
    asm volatile("ldmatrix.sync.aligned.m8n8.x4.shared.b16 {%0,%1,%2,%3}, [%4];" \
                 : "=r"(r0), "=r"(r1), "=r"(r2), "=r"(r3) : "r"(a))

__device__ __forceinline__ void mma_f16(float* d, const unsigned* a,
                                        unsigned b0, unsigned b1) {
    asm("mma.sync.aligned.m16n8k16.row.col.f32.f16.f16.f32 "
        "{%0,%1,%2,%3}, {%4,%5,%6,%7}, {%8,%9}, {%0,%1,%2,%3};"
        : "+f"(d[0]), "+f"(d[1]), "+f"(d[2]), "+f"(d[3])
        : "r"(a[0]), "r"(a[1]), "r"(a[2]), "r"(a[3]), "r"(b0), "r"(b1));
}

#define CP16(dst, src) \
    asm volatile("cp.async.cg.shared.global [%0], [%1], 16;" :: "r"(dst), "l"(src))
#define CP_COMMIT() asm volatile("cp.async.commit_group;" ::: "memory")
#define CP_WAIT0()  asm volatile("cp.async.wait_group 0;"  ::: "memory")

#define UPD(s1, i1, s2, i2, v, n)                          \
    do { if ((v) > (s1)) { s2 = s1; i2 = i1; s1 = (v); i1 = (n); } \
         else if ((v) > (s2)) { s2 = (v); i2 = (n); } } while (0)

__device__ __forceinline__ void merge2(float& s1, int& i1, float& s2, int& i2,
                                       float t1, int j1, float t2, int j2) {
    if (t1 > s1 || (t1 == s1 && j1 < i1)) {
        float ns2; int ni2;
        if (s1 > t2 || (s1 == t2 && i1 < j2)) { ns2 = s1; ni2 = i1; }
        else                                  { ns2 = t2; ni2 = j2; }
        s1 = t1; i1 = j1; s2 = ns2; i2 = ni2;
    } else if (t1 > s2 || (t1 == s2 && j1 < i2)) {
        s2 = t1; i2 = j1;
    }
}

__global__ void prep_keys_kernel(const float* __restrict__ keys) {
    int i = blockIdx.x * blockDim.x + threadIdx.x;
    if (i < M_KEYS * C_DIM) g_keys_h[i] = __float2half_rn(keys[i]);
}

__global__ __launch_bounds__(THREADS, 2)
void gathering_loss_kernel(const float* __restrict__ q,
                           const float* __restrict__ r,
                           const float* __restrict__ keys,
                           const float* __restrict__ values,
                           float* __restrict__ out)
{
    extern __shared__ char smem[];
    const unsigned sb = smem_u32(smem);
    const int tid  = threadIdx.x;
    const int lane = tid & 31;
    const int wid  = tid >> 5;          // 0..7, warp owns rows wid*16..+15
    const int row0 = blockIdx.x * BM;

    // ---- A tile: q rows -> fp16 smem [m][k], stride 272B ----
    {
        const float4* q4 = (const float4*)(q + (size_t)row0 * C_DIM);
        #pragma unroll
        for (int it = 0; it < (BM * C_DIM / 4) / THREADS; ++it) {
            int i = tid + it * THREADS;
            int m  = i >> 5;
            int k4 = (i & 31) << 2;
            float4 v = q4[i];
            __half2 h01 = __floats2half2_rn(v.x, v.y);
            __half2 h23 = __floats2half2_rn(v.z, v.w);
            char* p = smem + OFF_A + m * SAB + k4 * 2;
            *(__half2*)(p)     = h01;
            *(__half2*)(p + 4) = h23;
        }
    }

    auto load_b = [&](int chunk, int buf) {   // 128 keys = 32 KB
        const char* src = (const char*)(g_keys_h + (size_t)chunk * 128 * C_DIM);
        unsigned dst = sb + OFF_B(buf);
        #pragma unroll
        for (int it = 0; it < 8; ++it) {
            int s  = tid + it * THREADS;      // 2048 16B segments
            int n  = s >> 4;
            int ks = s & 15;
            CP16(dst + n * SAB + ks * 16, src + n * 256 + ks * 16);
        }
    };
    load_b(0, 0);
    CP_COMMIT();
    __syncthreads();                    // A tile visible

    // ---- persistent A fragments (32 regs) ----
    unsigned ahi[8][4];
    {
        int amat = lane >> 3;
        unsigned apart = sb + OFF_A
                       + (unsigned)(wid * 16 + (lane & 7) + ((amat & 1) << 3)) * SAB
                       + ((amat >> 1) << 4);
        #pragma unroll
        for (int ks = 0; ks < 8; ++ks)
            LDSM_X4(ahi[ks][0], ahi[ks][1], ahi[ks][2], ahi[ks][3], apart + ks * 32);
    }

    const int bmat = lane >> 3;
    const unsigned bpart = (unsigned)((lane & 7) + ((bmat >> 1) << 3)) * SAB
                         + ((bmat & 1) << 4);

    float s1a = -3.402823466e38f, s2a = -3.402823466e38f;
    float s1b = -3.402823466e38f, s2b = -3.402823466e38f;
    int i1a = 0, i2a = 0, i1b = 0, i2b = 0;

    #pragma unroll 1
    for (int c = 0; c < 8; ++c) {
        CP_WAIT0();                     // chunk-c data landed in buffer c&1
        __syncthreads();                // visible to all; all done with (c+1)&1
        if (c < 7) { load_b(c + 1, (c + 1) & 1); CP_COMMIT(); }

        const unsigned bbuf = sb + OFF_B(c & 1) + bpart;

        float acc[16][4];               // 16 independent HMMA chains
        #pragma unroll
        for (int nt = 0; nt < 16; ++nt)
            #pragma unroll
            for (int x = 0; x < 4; ++x) acc[nt][x] = 0.f;

        #pragma unroll
        for (int ks = 0; ks < 8; ++ks) {
            #pragma unroll
            for (int p = 0; p < 8; ++p) {      // pair p covers nt=2p, 2p+1
                unsigned b0, b1, b2, b3;
                LDSM_X4(b0, b1, b2, b3, bbuf + (unsigned)(p * 16) * SAB + ks * 32);
                mma_f16(acc[2 * p],     ahi[ks], b0, b1);
                mma_f16(acc[2 * p + 1], ahi[ks], b2, b3);
            }
        }

        // guarded top-2 update (ascending key index, strict > = first max)
        const int colbase = c * 128 + (lane & 3) * 2;
        #pragma unroll
        for (int nt = 0; nt < 16; ++nt) {
            int nb = colbase + nt * 8;
            float mxa = fmaxf(acc[nt][0], acc[nt][1]);
            if (mxa > s2a) {
                UPD(s1a, i1a, s2a, i2a, acc[nt][0], nb);
                UPD(s1a, i1a, s2a, i2a, acc[nt][1], nb + 1);
            }
            float mxb = fmaxf(acc[nt][2], acc[nt][3]);
            if (mxb > s2b) {
                UPD(s1b, i1b, s2b, i2b, acc[nt][2], nb);
                UPD(s1b, i1b, s2b, i2b, acc[nt][3], nb + 1);
            }
        }
    }
    __syncthreads();                    // compute done before smem reuse

    // ---- quad merge -> per-row top-2 over ALL 1024 keys ----
    #pragma unroll
    for (int off = 1; off <= 2; off <<= 1) {
        float t1 = __shfl_xor_sync(0xffffffffu, s1a, off);
        int   j1 = __shfl_xor_sync(0xffffffffu, i1a, off);
        float t2 = __shfl_xor_sync(0xffffffffu, s2a, off);
        int   j2 = __shfl_xor_sync(0xffffffffu, i2a, off);
        merge2(s1a, i1a, s2a, i2a, t1, j1, t2, j2);
        t1 = __shfl_xor_sync(0xffffffffu, s1b, off);
        j1 = __shfl_xor_sync(0xffffffffu, i1b, off);
        t2 = __shfl_xor_sync(0xffffffffu, s2b, off);
        j2 = __shfl_xor_sync(0xffffffffu, i2b, off);
        merge2(s1b, i1b, s2b, i2b, t1, j1, t2, j2);
    }

    int* ci = (int*)smem;               // [128][2] = 1KB, reuses A region
    if ((lane & 3) == 0) {
        int ra = wid * 16 + (lane >> 2);
        ci[ra * 2 + 0]       = i1a;  ci[ra * 2 + 1]       = i2a;
        ci[(ra + 8) * 2 + 0] = i1b;  ci[(ra + 8) * 2 + 1] = i2b;
    }
    __syncthreads();

    // ---- epilogue: 2 threads/row; exact fp32 rescore of 2 candidates + losses ----
    {
        int row  = tid >> 1;             // 0..127
        int half = tid & 1;
        int grow = row0 + row;
        int c1 = ci[row * 2 + 0];
        int c2 = ci[row * 2 + 1];

        const float4* qp = (const float4*)(q    + (size_t)grow * C_DIM + half * 64);
        const float4* ka = (const float4*)(keys + (size_t)c1   * C_DIM + half * 64);
        const float4* kb = (const float4*)(keys + (size_t)c2   * C_DIM + half * 64);
        float sa = 0.f, sc = 0.f;
        #pragma unroll
        for (int c = 0; c < 16; ++c) {
            float4 a = qp[c], x = ka[c], y = kb[c];
            sa = fmaf(a.x, x.x, sa); sa = fmaf(a.y, x.y, sa);
            sa = fmaf(a.z, x.z, sa); sa = fmaf(a.w, x.w, sa);
            sc = fmaf(a.x, y.x, sc); sc = fmaf(a.y, y.y, sc);
            sc = fmaf(a.z, y.z, sc); sc = fmaf(a.w, y.w, sc);
        }
        sa += __shfl_xor_sync(0xffffffffu, sa, 1);
        sc += __shfl_xor_sync(0xffffffffu, sc, 1);
        int bi = (sc > sa || (sc == sa && c2 < c1)) ? c2 : c1;

        const float4* kp = (const float4*)(keys   + (size_t)bi   * C_DIM + half * 64);
        const float4* rp = (const float4*)(r      + (size_t)grow * C_DIM + half * 64);
        const float4* vp = (const float4*)(values + (size_t)bi   * C_DIM + half * 64);
        float sk = 0.f, sv = 0.f;
        #pragma unroll
        for (int c = 0; c < 16; ++c) {
            float4 a = qp[c], b = kp[c];
            float d;
            d = a.x - b.x; sk = fmaf(d, d, sk);
            d = a.y - b.y; sk = fmaf(d, d, sk);
            d = a.z - b.z; sk = fmaf(d, d, sk);
            d = a.w - b.w; sk = fmaf(d, d, sk);
            float4 e = rp[c], f = vp[c];
            d = e.x - f.x; sv = fmaf(d, d, sv);
            d = e.y - f.y; sv = fmaf(d, d, sv);
            d = e.z - f.z; sv = fmaf(d, d, sv);
            d = e.w - f.w; sv = fmaf(d, d, sv);
        }
        sk += __shfl_xor_sync(0xffffffffu, sk, 1);
        sv += __shfl_xor_sync(0xffffffffu, sv, 1);
        if (half == 0) out[grow]           = sk;
        else           out[T_TOTAL + grow] = sv;
    }
}

extern "C" void kernel_launch(void* const* d_in, const int* in_sizes, int n_in,
                              void* d_out, int out_size)
{
    const float* q      = (const float*)d_in[0];
    const float* r      = (const float*)d_in[1];
    const float* keys   = (const float*)d_in[2];
    const float* values = (const float*)d_in[3];
    float* out = (float*)d_out;

    prep_keys_kernel<<<(M_KEYS * C_DIM + 255) / 256, 256>>>(keys);

    cudaFuncSetAttribute(gathering_loss_kernel,
                         cudaFuncAttributeMaxDynamicSharedMemorySize, SM_TOTAL);
    gathering_loss_kernel<<<T_TOTAL / BM, THREADS, SM_TOTAL>>>(q, r, keys, values, out);
}